// round 9
// baseline (speedup 1.0000x reference)
#include <cuda_runtime.h>

// CELossWithLS: focal-weighted label-smoothed CE, single fused kernel.
// logits: [B*S, C] f32 (C = 10000), target: [B*S] int32, out: scalar f32.
//
// per_tok = -( 1e-5 * sum_i (1-p_i)^3 * logs_i  +  0.9 * (1-p_t)^3 * logs_t )
// sum_i (1-p)^3 logs = (Sx - C*L) - 3*(B1/A1 - L) + O(1.5e-5 abs),
// A1 = sum e^x, B1 = sum x e^x, L = log(A1). Validated r3-r8: rel_err = 0.0.
//
// r8 finding: a second launch has a ~3.5-7us graph-replay floor regardless of
// its work. Fusion matrix deconfounded: r4 (unroll4/56r), r5 (32r cap),
// r6 (f32x2) each damaged the STREAMING LOOP, not the fusion. This round runs
// the untested cell: r3's exact unroll-2 loop + free codegen
// (__launch_bounds__(256,1)) + lean last-block epilogue (float partials,
// vectorized loads, doubles only at the 8-warp combine).

#define NCLASS  10000
#define NVEC    (NCLASS / 4)   // 2500 float4 per row
#define THREADS 256
#define MAXTOK  16384

__device__ float        g_per[MAXTOK];
__device__ unsigned int g_arrive = 0;   // reset to 0 by last CTA each call

__global__ __launch_bounds__(THREADS, 1) void ce_fused(
    const float* __restrict__ logits,
    const int*   __restrict__ target,
    float*       __restrict__ out,
    const int    ntok)
{
    const int row = blockIdx.x;
    const int tgt = __ldg(&target[row]);

    const float4* __restrict__ p =
        reinterpret_cast<const float4*>(logits) + (size_t)row * NVEC;

    float sx = 0.0f;   // sum x
    float a1 = 0.0f;   // sum e^x
    float b1 = 0.0f;   // sum x * e^x

    #pragma unroll 2
    for (int i = threadIdx.x; i < NVEC; i += THREADS) {
        float4 v = p[i];
        float e;
        e = __expf(v.x); sx += v.x; a1 += e; b1 = fmaf(v.x, e, b1);
        e = __expf(v.y); sx += v.y; a1 += e; b1 = fmaf(v.y, e, b1);
        e = __expf(v.z); sx += v.z; a1 += e; b1 = fmaf(v.z, e, b1);
        e = __expf(v.w); sx += v.w; a1 += e; b1 = fmaf(v.w, e, b1);
    }

    // intra-warp tree reduce (3 values)
    #pragma unroll
    for (int o = 16; o > 0; o >>= 1) {
        sx += __shfl_down_sync(0xffffffffu, sx, o);
        a1 += __shfl_down_sync(0xffffffffu, a1, o);
        b1 += __shfl_down_sync(0xffffffffu, b1, o);
    }

    __shared__ float s_sx[THREADS / 32];
    __shared__ float s_a1[THREADS / 32];
    __shared__ float s_b1[THREADS / 32];
    __shared__ int   s_last;
    const int lane = threadIdx.x & 31;
    const int wrp  = threadIdx.x >> 5;
    if (lane == 0) { s_sx[wrp] = sx; s_a1[wrp] = a1; s_b1[wrp] = b1; }
    __syncthreads();

    if (threadIdx.x == 0) {
        float SX = 0.0f, A1 = 0.0f, B1 = 0.0f;
        #pragma unroll
        for (int k = 0; k < THREADS / 32; k++) {
            SX += s_sx[k]; A1 += s_a1[k]; B1 += s_b1[k];
        }
        float per_tok = 0.0f;
        if (tgt != -1) {
            // accurate log: its error is multiplied by C=1e4 in (SX - C*L)
            float L  = logf(A1);
            float S3 = (SX - (float)NCLASS * L) - 3.0f * (B1 / A1 - L);
            per_tok = -1e-5f * S3;
            if (tgt >= 0 && tgt < NCLASS) {      // bound-checked gather
                float xt = __ldg(&logits[(size_t)row * NCLASS + tgt]);
                float lt = xt - L;
                float pt = __expf(lt);
                float om = 1.0f - pt;
                per_tok -= 0.9f * om * om * om * lt;
            }
        }
        g_per[row] = per_tok;

        __threadfence();                          // release partial
        unsigned prev = atomicAdd(&g_arrive, 1u);
        s_last = (prev == (unsigned)(ntok - 1)) ? 1 : 0;
    }
    __syncthreads();

    // Last CTA: vectorized final reduce (ntok = 8192 is a multiple of 4).
    // Partials were written moments ago -> mostly L2-resident; 8 independent
    // float4+int4 loads per thread, front-batched.
    if (s_last) {
        __threadfence();                          // acquire all partials
        const int nvec4 = ntok >> 2;
        const int4* __restrict__ t4 = reinterpret_cast<const int4*>(target);

        float acc = 0.0f;
        int   cnt = 0;
        for (int i = threadIdx.x; i < nvec4; i += THREADS) {
            float4 v = *reinterpret_cast<const float4*>(&g_per[i << 2]);
            int4   t = t4[i];
            acc += (v.x + v.y) + (v.z + v.w);
            cnt += (t.x != -1) + (t.y != -1) + (t.z != -1) + (t.w != -1);
        }

        double dacc = (double)acc;
        #pragma unroll
        for (int o = 16; o > 0; o >>= 1) {
            dacc += __shfl_down_sync(0xffffffffu, dacc, o);
            cnt  += __shfl_down_sync(0xffffffffu, cnt, o);
        }
        __shared__ double f_acc[THREADS / 32];
        __shared__ int    f_cnt[THREADS / 32];
        if (lane == 0) { f_acc[wrp] = dacc; f_cnt[wrp] = cnt; }
        __syncthreads();
        if (threadIdx.x == 0) {
            double A = 0.0; int Cn = 0;
            #pragma unroll
            for (int k = 0; k < THREADS / 32; k++) { A += f_acc[k]; Cn += f_cnt[k]; }
            out[0] = (float)(A / (double)Cn);
            g_arrive = 0;                         // reset for next replay
        }
    }
}

extern "C" void kernel_launch(void* const* d_in, const int* in_sizes, int n_in,
                              void* d_out, int out_size)
{
    const float* logits = (const float*)d_in[0];
    const int*   target = (const int*)d_in[1];
    const int ntok = in_sizes[1];          // B*S tokens

    ce_fused<<<ntok, THREADS>>>(logits, target, (float*)d_out, ntok);
}

// round 10
// speedup vs baseline: 1.3996x; 1.3996x over previous
#include <cuda_runtime.h>

// CELossWithLS: focal-weighted label-smoothed CE, single fused kernel with a
// ZERO-pressure epilogue.
// logits: [B*S, C] f32 (C = 10000), target: [B*S] int32, out: scalar f32.
//
// per_tok = -( 1e-5 * sum_i (1-p_i)^3 * logs_i  +  0.9 * (1-p_t)^3 * logs_t )
// sum_i (1-p)^3 logs = (Sx - C*L) - 3*(B1/A1 - L) + O(1.5e-5 abs),
// A1 = sum e^x, B1 = sum x e^x, L = log(A1). Validated r3-r9: rel_err = 0.0.
//
// Evidence matrix: streaming loop w/ free codegen = 51.5us; ANY kernel that
// also contains a bulk reduce epilogue (loops/doubles/vector loads) -> 56
// regs -> 4 CTAs -> ~80us; a second launch costs a fixed ~6us replay floor.
// This round: fuse with an epilogue of ~10 scalar instructions in thread 0's
// existing branch: float atomicAdd of per_tok + ONE packed u64 atomic that is
// simultaneously arrival counter (hi 32) and valid-token counter (lo 32).
// Last arriver atomicExch-reads+resets the sum, writes out, resets the pack.
// Fully self-resetting -> no init kernel, deterministic across replays.

#define NCLASS  10000
#define NVEC    (NCLASS / 4)   // 2500 float4 per row
#define THREADS 256

__device__ float              g_sum  = 0.0f;  // reset by last CTA each call
__device__ unsigned long long g_pack = 0ull;  // hi: arrivals, lo: valid count

__global__ __launch_bounds__(THREADS, 1) void ce_fused(
    const float* __restrict__ logits,
    const int*   __restrict__ target,
    float*       __restrict__ out,
    const int    ntok)
{
    const int row = blockIdx.x;
    const int tgt = __ldg(&target[row]);

    const float4* __restrict__ p =
        reinterpret_cast<const float4*>(logits) + (size_t)row * NVEC;

    float sx = 0.0f;   // sum x
    float a1 = 0.0f;   // sum e^x
    float b1 = 0.0f;   // sum x * e^x

    #pragma unroll 2
    for (int i = threadIdx.x; i < NVEC; i += THREADS) {
        float4 v = p[i];
        float e;
        e = __expf(v.x); sx += v.x; a1 += e; b1 = fmaf(v.x, e, b1);
        e = __expf(v.y); sx += v.y; a1 += e; b1 = fmaf(v.y, e, b1);
        e = __expf(v.z); sx += v.z; a1 += e; b1 = fmaf(v.z, e, b1);
        e = __expf(v.w); sx += v.w; a1 += e; b1 = fmaf(v.w, e, b1);
    }

    // intra-warp tree reduce (3 values)
    #pragma unroll
    for (int o = 16; o > 0; o >>= 1) {
        sx += __shfl_down_sync(0xffffffffu, sx, o);
        a1 += __shfl_down_sync(0xffffffffu, a1, o);
        b1 += __shfl_down_sync(0xffffffffu, b1, o);
    }

    __shared__ float s_sx[THREADS / 32];
    __shared__ float s_a1[THREADS / 32];
    __shared__ float s_b1[THREADS / 32];
    const int lane = threadIdx.x & 31;
    const int wrp  = threadIdx.x >> 5;
    if (lane == 0) { s_sx[wrp] = sx; s_a1[wrp] = a1; s_b1[wrp] = b1; }
    __syncthreads();

    if (threadIdx.x == 0) {
        float SX = 0.0f, A1 = 0.0f, B1 = 0.0f;
        #pragma unroll
        for (int k = 0; k < THREADS / 32; k++) {
            SX += s_sx[k]; A1 += s_a1[k]; B1 += s_b1[k];
        }

        unsigned valid = 0u;
        if (tgt != -1) {
            // accurate log: its error is multiplied by C=1e4 in (SX - C*L)
            float L  = logf(A1);
            float S3 = (SX - (float)NCLASS * L) - 3.0f * (B1 / A1 - L);
            float per_tok = -1e-5f * S3;
            if (tgt >= 0 && tgt < NCLASS) {      // bound-checked gather
                float xt = __ldg(&logits[(size_t)row * NCLASS + tgt]);
                float lt = xt - L;
                float pt = __expf(lt);
                float om = 1.0f - pt;
                per_tok -= 0.9f * om * om * om * lt;
            }
            atomicAdd(&g_sum, per_tok);
            valid = 1u;
        }

        __threadfence();                          // sum-add visible before pack-add
        unsigned long long prev =
            atomicAdd(&g_pack, 0x100000000ull + (unsigned long long)valid);
        unsigned arrived = (unsigned)(prev >> 32);

        if (arrived == (unsigned)(ntok - 1)) {    // I am the last CTA
            __threadfence();                      // acquire all sum-adds
            unsigned cnt = (unsigned)(prev & 0xffffffffu) + valid;
            float total = atomicExch(&g_sum, 0.0f);   // read + reset
            out[0] = total / (float)cnt;
            g_pack = 0ull;                        // reset for next replay
        }
    }
}

extern "C" void kernel_launch(void* const* d_in, const int* in_sizes, int n_in,
                              void* d_out, int out_size)
{
    const float* logits = (const float*)d_in[0];
    const int*   target = (const int*)d_in[1];
    const int ntok = in_sizes[1];          // B*S tokens

    ce_fused<<<ntok, THREADS>>>(logits, target, (float*)d_out, ntok);
}

// round 11
// speedup vs baseline: 1.4461x; 1.0333x over previous
#include <cuda_runtime.h>

// CELossWithLS: focal-weighted label-smoothed CE, single fused kernel,
// zero-pressure atomic epilogue + explicitly batched streaming loads.
// logits: [B*S, C] f32 (C = 10000), target: [B*S] int32, out: scalar f32.
//
// per_tok = -( 1e-5 * sum_i (1-p_i)^3 * logs_i  +  0.9 * (1-p_t)^3 * logs_t )
// sum_i (1-p)^3 logs = (Sx - C*L) - 3*(B1/A1 - L) + O(1.5e-5 abs),
// A1 = sum e^x, B1 = sum x e^x, L = log(A1). rel_err 6.9e-7 measured (r10).
//
// r10 finding: epilogue solved (30 regs, single launch), but 30 regs is TOO
// low -- ptxas interleaves load->consume (can't hold 2 float4 live) -> DRAM
// 76%. Ten-round pattern: DRAM% tracks per-warp load batching, not occupancy.
// This round: force batching by loading p[i] and p[i+256] into distinct vars
// before any math (r6's structure minus f32x2 churn minus the reg cap), plus
// __ldcs evict-first on the once-read stream. Epilogue unchanged.

#define NCLASS  10000
#define NVEC    (NCLASS / 4)   // 2500 float4 per row
#define THREADS 256

__device__ float              g_sum  = 0.0f;  // reset by last CTA each call
__device__ unsigned long long g_pack = 0ull;  // hi: arrivals, lo: valid count

__device__ __forceinline__ void proc4(const float4 v,
                                      float& sx, float& a1, float& b1) {
    float e;
    e = __expf(v.x); sx += v.x; a1 += e; b1 = fmaf(v.x, e, b1);
    e = __expf(v.y); sx += v.y; a1 += e; b1 = fmaf(v.y, e, b1);
    e = __expf(v.z); sx += v.z; a1 += e; b1 = fmaf(v.z, e, b1);
    e = __expf(v.w); sx += v.w; a1 += e; b1 = fmaf(v.w, e, b1);
}

__global__ __launch_bounds__(THREADS, 1) void ce_fused(
    const float* __restrict__ logits,
    const int*   __restrict__ target,
    float*       __restrict__ out,
    const int    ntok)
{
    const int row = blockIdx.x;
    const int tgt = __ldg(&target[row]);

    const float4* __restrict__ p =
        reinterpret_cast<const float4*>(logits) + (size_t)row * NVEC;

    float sx = 0.0f;   // sum x
    float a1 = 0.0f;   // sum e^x
    float b1 = 0.0f;   // sum x * e^x

    // 2-deep batched stream: both LDG.128s issued before any math.
    // NVEC = 2500: threads 0..195 run 5 paired iters (i reaches 2308+..2500);
    // threads 196..255 run 4 paired + 1 remainder.
    int i = threadIdx.x;
    #pragma unroll 1
    for (; i + THREADS < NVEC; i += 2 * THREADS) {
        float4 v0 = __ldcs(&p[i]);
        float4 v1 = __ldcs(&p[i + THREADS]);
        proc4(v0, sx, a1, b1);
        proc4(v1, sx, a1, b1);
    }
    if (i < NVEC) {
        float4 v = __ldcs(&p[i]);
        proc4(v, sx, a1, b1);
    }

    // intra-warp tree reduce (3 values)
    #pragma unroll
    for (int o = 16; o > 0; o >>= 1) {
        sx += __shfl_down_sync(0xffffffffu, sx, o);
        a1 += __shfl_down_sync(0xffffffffu, a1, o);
        b1 += __shfl_down_sync(0xffffffffu, b1, o);
    }

    __shared__ float s_sx[THREADS / 32];
    __shared__ float s_a1[THREADS / 32];
    __shared__ float s_b1[THREADS / 32];
    const int lane = threadIdx.x & 31;
    const int wrp  = threadIdx.x >> 5;
    if (lane == 0) { s_sx[wrp] = sx; s_a1[wrp] = a1; s_b1[wrp] = b1; }
    __syncthreads();

    if (threadIdx.x == 0) {
        float SX = 0.0f, A1 = 0.0f, B1 = 0.0f;
        #pragma unroll
        for (int k = 0; k < THREADS / 32; k++) {
            SX += s_sx[k]; A1 += s_a1[k]; B1 += s_b1[k];
        }

        unsigned valid = 0u;
        if (tgt != -1) {
            // accurate log: its error is multiplied by C=1e4 in (SX - C*L)
            float L  = logf(A1);
            float S3 = (SX - (float)NCLASS * L) - 3.0f * (B1 / A1 - L);
            float per_tok = -1e-5f * S3;
            if (tgt >= 0 && tgt < NCLASS) {      // bound-checked gather
                float xt = __ldg(&logits[(size_t)row * NCLASS + tgt]);
                float lt = xt - L;
                float pt = __expf(lt);
                float om = 1.0f - pt;
                per_tok -= 0.9f * om * om * om * lt;
            }
            atomicAdd(&g_sum, per_tok);
            valid = 1u;
        }

        __threadfence();                          // sum-add visible before pack-add
        unsigned long long prev =
            atomicAdd(&g_pack, 0x100000000ull + (unsigned long long)valid);
        unsigned arrived = (unsigned)(prev >> 32);

        if (arrived == (unsigned)(ntok - 1)) {    // I am the last CTA
            __threadfence();                      // acquire all sum-adds
            unsigned cnt = (unsigned)(prev & 0xffffffffu) + valid;
            float total = atomicExch(&g_sum, 0.0f);   // read + reset
            out[0] = total / (float)cnt;
            g_pack = 0ull;                        // reset for next replay
        }
    }
}

extern "C" void kernel_launch(void* const* d_in, const int* in_sizes, int n_in,
                              void* d_out, int out_size)
{
    const float* logits = (const float*)d_in[0];
    const int*   target = (const int*)d_in[1];
    const int ntok = in_sizes[1];          // B*S tokens

    ce_fused<<<ntok, THREADS>>>(logits, target, (float*)d_out, ntok);
}